// round 1
// baseline (speedup 1.0000x reference)
#include <cuda_runtime.h>
#include <cuda_bf16.h>
#include <stdint.h>

namespace {

constexpr int Bb = 4, Ss = 2048, Hh = 16, Dd = 64;
constexpr int BM = 64, BN = 64;
constexpr int PAD = 68;           // floats per smem row: conflict-free frag reads, 16B-aligned rows
constexpr float SCALE = 0.125f;   // 1/sqrt(64)
constexpr float NEGINF = -1e30f;

__device__ __forceinline__ uint32_t f2tf32(float f) {
    uint32_t r;
    asm("cvt.rna.tf32.f32 %0, %1;" : "=r"(r) : "f"(f));
    return r;
}

// pack two floats -> bf16x2 (lower half = lo, upper half = hi)
__device__ __forceinline__ uint32_t packbf2(float lo, float hi) {
    uint32_t r;
    asm("cvt.rn.bf16x2.f32 %0, %1, %2;" : "=r"(r) : "f"(hi), "f"(lo));
    return r;
}

__device__ __forceinline__ void mma_tf32(float c[4], const uint32_t a[4], const uint32_t b[2]) {
    asm volatile(
        "mma.sync.aligned.m16n8k8.row.col.f32.tf32.tf32.f32 "
        "{%0,%1,%2,%3}, {%4,%5,%6,%7}, {%8,%9}, {%0,%1,%2,%3};"
        : "+f"(c[0]), "+f"(c[1]), "+f"(c[2]), "+f"(c[3])
        : "r"(a[0]), "r"(a[1]), "r"(a[2]), "r"(a[3]), "r"(b[0]), "r"(b[1]));
}

__device__ __forceinline__ void mma_bf16(float c[4], const uint32_t a[4], const uint32_t b[2]) {
    asm volatile(
        "mma.sync.aligned.m16n8k16.row.col.f32.bf16.bf16.f32 "
        "{%0,%1,%2,%3}, {%4,%5,%6,%7}, {%8,%9}, {%0,%1,%2,%3};"
        : "+f"(c[0]), "+f"(c[1]), "+f"(c[2]), "+f"(c[3])
        : "r"(a[0]), "r"(a[1]), "r"(a[2]), "r"(a[3]), "r"(b[0]), "r"(b[1]));
}

__global__ void __launch_bounds__(128, 2)
fa_kernel(const float* __restrict__ q, const float* __restrict__ k,
          const float* __restrict__ v, const float* __restrict__ bias,
          float* __restrict__ out)
{
    __shared__ __align__(16) float sK[BN * PAD];   // [n][d]
    __shared__ __align__(16) float sV[BN * PAD];   // [n][d]

    const int tid  = threadIdx.x;
    const int lane = tid & 31;
    const int wid  = tid >> 5;
    const int g    = lane >> 2;   // row group within fragment
    const int c    = lane & 3;    // thread-in-group

    // grid: batch fastest-varying so the 4 CTAs sharing a bias tile are adjacent (L2 reuse)
    const int idx = blockIdx.x;
    const int b   = idx & 3;
    const int h   = (idx >> 2) & 15;
    const int qt  = idx >> 6;

    const int r0 = qt * BM + wid * 16 + g;   // global q row for c0,c1
    const int r1 = r0 + 8;                   // global q row for c2,c3

    // ---- Q fragments (tf32), loaded once ----
    const float* q0 = q + ((size_t)(b * Ss + r0) * Hh + h) * Dd;
    const float* q1 = q + ((size_t)(b * Ss + r1) * Hh + h) * Dd;
    uint32_t qa[8][4];
#pragma unroll
    for (int ks = 0; ks < 8; ks++) {
        const int d0 = ks * 8 + c;
        qa[ks][0] = f2tf32(q0[d0]);
        qa[ks][1] = f2tf32(q1[d0]);
        qa[ks][2] = f2tf32(q0[d0 + 4]);
        qa[ks][3] = f2tf32(q1[d0 + 4]);
    }

    float oacc[8][4];
#pragma unroll
    for (int i = 0; i < 8; i++) {
        oacc[i][0] = 0.f; oacc[i][1] = 0.f; oacc[i][2] = 0.f; oacc[i][3] = 0.f;
    }
    float m0 = NEGINF, m1 = NEGINF, l0 = 0.f, l1 = 0.f;

    const float* biasr0 = bias + ((size_t)h * Ss + r0) * Ss;
    const float* biasr1 = bias + ((size_t)h * Ss + r1) * Ss;

    for (int j = 0; j <= qt; j++) {
        __syncthreads();
        // ---- cooperative load of K,V tiles (fp32, coalesced float4) ----
        {
            const size_t base = ((size_t)(b * Ss + j * BN) * Hh + h) * Dd;
#pragma unroll
            for (int it = 0; it < 8; it++) {
                const int t  = it * 128 + tid;
                const int n  = t >> 4;
                const int d4 = (t & 15) << 2;
                const size_t off = base + (size_t)n * (Hh * Dd) + d4;
                const float4 kv = *(const float4*)(k + off);
                const float4 vv = *(const float4*)(v + off);
                *(float4*)(&sK[n * PAD + d4]) = kv;
                *(float4*)(&sV[n * PAD + d4]) = vv;
            }
        }
        __syncthreads();

        // ---- S = Q K^T (tf32 mma) ----
        float sacc[8][4];
#pragma unroll
        for (int nf = 0; nf < 8; nf++) {
            sacc[nf][0] = 0.f; sacc[nf][1] = 0.f; sacc[nf][2] = 0.f; sacc[nf][3] = 0.f;
#pragma unroll
            for (int ks = 0; ks < 8; ks++) {
                const float* kp = &sK[(nf * 8 + g) * PAD + ks * 8 + c];
                uint32_t bfr[2];
                bfr[0] = f2tf32(kp[0]);
                bfr[1] = f2tf32(kp[4]);
                mma_tf32(sacc[nf], qa[ks], bfr);
            }
        }

        // ---- scale + bias + causal mask ----
        const int kcb = j * BN;
        const bool diag = (j == qt);
#pragma unroll
        for (int nf = 0; nf < 8; nf++) {
            const int kc = kcb + nf * 8 + 2 * c;
            const float2 bb0 = __ldg((const float2*)(biasr0 + kc));
            const float2 bb1 = __ldg((const float2*)(biasr1 + kc));
            sacc[nf][0] = sacc[nf][0] * SCALE + bb0.x;
            sacc[nf][1] = sacc[nf][1] * SCALE + bb0.y;
            sacc[nf][2] = sacc[nf][2] * SCALE + bb1.x;
            sacc[nf][3] = sacc[nf][3] * SCALE + bb1.y;
            if (diag) {
                if (kc     > r0) sacc[nf][0] = NEGINF;
                if (kc + 1 > r0) sacc[nf][1] = NEGINF;
                if (kc     > r1) sacc[nf][2] = NEGINF;
                if (kc + 1 > r1) sacc[nf][3] = NEGINF;
            }
        }

        // ---- online softmax ----
        float rm0 = NEGINF, rm1 = NEGINF;
#pragma unroll
        for (int nf = 0; nf < 8; nf++) {
            rm0 = fmaxf(rm0, fmaxf(sacc[nf][0], sacc[nf][1]));
            rm1 = fmaxf(rm1, fmaxf(sacc[nf][2], sacc[nf][3]));
        }
        rm0 = fmaxf(rm0, __shfl_xor_sync(0xffffffffu, rm0, 1));
        rm0 = fmaxf(rm0, __shfl_xor_sync(0xffffffffu, rm0, 2));
        rm1 = fmaxf(rm1, __shfl_xor_sync(0xffffffffu, rm1, 1));
        rm1 = fmaxf(rm1, __shfl_xor_sync(0xffffffffu, rm1, 2));

        const float nm0 = fmaxf(m0, rm0), nm1 = fmaxf(m1, rm1);
        const float a0 = __expf(m0 - nm0), a1 = __expf(m1 - nm1);
        m0 = nm0; m1 = nm1;

        float rs0 = 0.f, rs1 = 0.f;
#pragma unroll
        for (int nf = 0; nf < 8; nf++) {
            sacc[nf][0] = __expf(sacc[nf][0] - nm0);
            sacc[nf][1] = __expf(sacc[nf][1] - nm0);
            sacc[nf][2] = __expf(sacc[nf][2] - nm1);
            sacc[nf][3] = __expf(sacc[nf][3] - nm1);
            rs0 += sacc[nf][0] + sacc[nf][1];
            rs1 += sacc[nf][2] + sacc[nf][3];
        }
        l0 = l0 * a0 + rs0;   // quad reduction deferred to epilogue (linear in lanes)
        l1 = l1 * a1 + rs1;

#pragma unroll
        for (int df = 0; df < 8; df++) {
            oacc[df][0] *= a0; oacc[df][1] *= a0;
            oacc[df][2] *= a1; oacc[df][3] *= a1;
        }

        // ---- O += P V  (split-bf16: p_hi*v_hi + p_hi*v_lo + p_lo*v_hi) ----
#pragma unroll
        for (int t = 0; t < 4; t++) {
            uint32_t ahi[4], alo[4];
            {
                const float p00 = sacc[2 * t][0],     p01 = sacc[2 * t][1];
                const float p10 = sacc[2 * t][2],     p11 = sacc[2 * t][3];
                const float p20 = sacc[2 * t + 1][0], p21 = sacc[2 * t + 1][1];
                const float p30 = sacc[2 * t + 1][2], p31 = sacc[2 * t + 1][3];
                ahi[0] = packbf2(p00, p01);
                ahi[1] = packbf2(p10, p11);
                ahi[2] = packbf2(p20, p21);
                ahi[3] = packbf2(p30, p31);
                alo[0] = packbf2(p00 - __uint_as_float(ahi[0] << 16),
                                 p01 - __uint_as_float(ahi[0] & 0xffff0000u));
                alo[1] = packbf2(p10 - __uint_as_float(ahi[1] << 16),
                                 p11 - __uint_as_float(ahi[1] & 0xffff0000u));
                alo[2] = packbf2(p20 - __uint_as_float(ahi[2] << 16),
                                 p21 - __uint_as_float(ahi[2] & 0xffff0000u));
                alo[3] = packbf2(p30 - __uint_as_float(ahi[3] << 16),
                                 p31 - __uint_as_float(ahi[3] & 0xffff0000u));
            }
#pragma unroll
            for (int df = 0; df < 8; df++) {
                const float* vp = &sV[(t * 16 + 2 * c) * PAD + df * 8 + g];
                const float v0 = vp[0];
                const float v1 = vp[PAD];
                const float v2 = vp[8 * PAD];
                const float v3 = vp[9 * PAD];
                uint32_t bhi[2], blo[2];
                bhi[0] = packbf2(v0, v1);
                bhi[1] = packbf2(v2, v3);
                blo[0] = packbf2(v0 - __uint_as_float(bhi[0] << 16),
                                 v1 - __uint_as_float(bhi[0] & 0xffff0000u));
                blo[1] = packbf2(v2 - __uint_as_float(bhi[1] << 16),
                                 v3 - __uint_as_float(bhi[1] & 0xffff0000u));
                mma_bf16(oacc[df], ahi, bhi);
                mma_bf16(oacc[df], ahi, blo);
                mma_bf16(oacc[df], alo, bhi);
            }
        }
    }

    // ---- epilogue: finish l reduction, normalize, store ----
    l0 += __shfl_xor_sync(0xffffffffu, l0, 1);
    l0 += __shfl_xor_sync(0xffffffffu, l0, 2);
    l1 += __shfl_xor_sync(0xffffffffu, l1, 1);
    l1 += __shfl_xor_sync(0xffffffffu, l1, 2);
    const float inv0 = 1.0f / l0;
    const float inv1 = 1.0f / l1;

    float* o0 = out + ((size_t)(b * Ss + r0) * Hh + h) * Dd;
    float* o1 = out + ((size_t)(b * Ss + r1) * Hh + h) * Dd;
#pragma unroll
    for (int df = 0; df < 8; df++) {
        const int dc = df * 8 + 2 * c;
        float2 w0, w1;
        w0.x = oacc[df][0] * inv0; w0.y = oacc[df][1] * inv0;
        w1.x = oacc[df][2] * inv1; w1.y = oacc[df][3] * inv1;
        *(float2*)(o0 + dc) = w0;
        *(float2*)(o1 + dc) = w1;
    }
}

} // namespace

extern "C" void kernel_launch(void* const* d_in, const int* in_sizes, int n_in,
                              void* d_out, int out_size)
{
    const float* q    = (const float*)d_in[0];
    const float* k    = (const float*)d_in[1];
    const float* v    = (const float*)d_in[2];
    const float* bias = (const float*)d_in[3];
    float* out        = (float*)d_out;

    const dim3 grid(Bb * Hh * (Ss / BM));  // 2048 CTAs, batch fastest-varying
    fa_kernel<<<grid, 128>>>(q, k, v, bias, out);
}

// round 2
// speedup vs baseline: 1.2348x; 1.2348x over previous
#include <cuda_runtime.h>
#include <cuda_bf16.h>
#include <stdint.h>

namespace {

constexpr int Bb = 4, Ss = 2048, Hh = 16, Dd = 64;
constexpr int BM = 64, BN = 64;
constexpr int PAD = 68;           // uint32 per sK row: bank = 4g+c, conflict-free
constexpr int VP  = 72;           // uint32 per sVhi/sVlo row: bank = 8c+g, conflict-free
constexpr float SCALE = 0.125f;   // 1/sqrt(64)
constexpr float NEGINF = -1e30f;

__device__ __forceinline__ uint32_t f2tf32(float f) {
    uint32_t r;
    asm("cvt.rna.tf32.f32 %0, %1;" : "=r"(r) : "f"(f));
    return r;
}

// pack two floats -> bf16x2 (lower half = lo arg, upper half = hi arg)
__device__ __forceinline__ uint32_t packbf2(float lo, float hi) {
    uint32_t r;
    asm("cvt.rn.bf16x2.f32 %0, %1, %2;" : "=r"(r) : "f"(hi), "f"(lo));
    return r;
}

__device__ __forceinline__ void mma_tf32(float c[4], const uint32_t a[4], const uint32_t b[2]) {
    asm volatile(
        "mma.sync.aligned.m16n8k8.row.col.f32.tf32.tf32.f32 "
        "{%0,%1,%2,%3}, {%4,%5,%6,%7}, {%8,%9}, {%0,%1,%2,%3};"
        : "+f"(c[0]), "+f"(c[1]), "+f"(c[2]), "+f"(c[3])
        : "r"(a[0]), "r"(a[1]), "r"(a[2]), "r"(a[3]), "r"(b[0]), "r"(b[1]));
}

__device__ __forceinline__ void mma_bf16(float c[4], const uint32_t a[4], const uint32_t b[2]) {
    asm volatile(
        "mma.sync.aligned.m16n8k16.row.col.f32.bf16.bf16.f32 "
        "{%0,%1,%2,%3}, {%4,%5,%6,%7}, {%8,%9}, {%0,%1,%2,%3};"
        : "+f"(c[0]), "+f"(c[1]), "+f"(c[2]), "+f"(c[3])
        : "r"(a[0]), "r"(a[1]), "r"(a[2]), "r"(a[3]), "r"(b[0]), "r"(b[1]));
}

__global__ void __launch_bounds__(128, 2)
fa_kernel(const float* __restrict__ q, const float* __restrict__ k,
          const float* __restrict__ v, const float* __restrict__ bias,
          float* __restrict__ out)
{
    __shared__ __align__(16) uint32_t sK[BN * PAD];      // K tile, pre-converted tf32, [n][d]
    __shared__ __align__(16) uint32_t sVhi[(BN/2) * VP]; // V tile, bf16x2 (row2rp | row2rp+1), hi part
    __shared__ __align__(16) uint32_t sVlo[(BN/2) * VP]; // V tile, bf16x2 residual, lo part

    const int tid  = threadIdx.x;
    const int lane = tid & 31;
    const int wid  = tid >> 5;
    const int g    = lane >> 2;   // row group within fragment
    const int c    = lane & 3;    // thread-in-group

    // grid: batch fastest-varying (bias L2 reuse); qt reversed (longest CTAs first)
    const int idx = blockIdx.x;
    const int b   = idx & 3;
    const int h   = (idx >> 2) & 15;
    const int qt  = (Ss / BM - 1) - (idx >> 6);

    const int r0 = qt * BM + wid * 16 + g;   // global q row for c0,c1
    const int r1 = r0 + 8;                   // global q row for c2,c3

    // ---- Q fragments (tf32), loaded once ----
    const float* q0 = q + ((size_t)(b * Ss + r0) * Hh + h) * Dd;
    const float* q1 = q + ((size_t)(b * Ss + r1) * Hh + h) * Dd;
    uint32_t qa[8][4];
#pragma unroll
    for (int ks = 0; ks < 8; ks++) {
        const int d0 = ks * 8 + c;
        qa[ks][0] = f2tf32(q0[d0]);
        qa[ks][1] = f2tf32(q1[d0]);
        qa[ks][2] = f2tf32(q0[d0 + 4]);
        qa[ks][3] = f2tf32(q1[d0 + 4]);
    }

    float oacc[8][4];
#pragma unroll
    for (int i = 0; i < 8; i++) {
        oacc[i][0] = 0.f; oacc[i][1] = 0.f; oacc[i][2] = 0.f; oacc[i][3] = 0.f;
    }
    float m0 = NEGINF, m1 = NEGINF, l0 = 0.f, l1 = 0.f;

    const float* biasr0 = bias + ((size_t)h * Ss + r0) * Ss;
    const float* biasr1 = bias + ((size_t)h * Ss + r1) * Ss;

    for (int j = 0; j <= qt; j++) {
        __syncthreads();
        const size_t base = ((size_t)(b * Ss + j * BN) * Hh + h) * Dd;

        // ---- K tile: load fp32, convert to tf32 ONCE, store to smem ----
#pragma unroll
        for (int it = 0; it < 8; it++) {
            const int t  = it * 128 + tid;
            const int n  = t >> 4;
            const int d4 = (t & 15) << 2;
            const float4 kv = *(const float4*)(k + base + (size_t)n * (Hh * Dd) + d4);
            uint4 kt;
            kt.x = f2tf32(kv.x); kt.y = f2tf32(kv.y);
            kt.z = f2tf32(kv.z); kt.w = f2tf32(kv.w);
            *(uint4*)(&sK[n * PAD + d4]) = kt;
        }

        // ---- V tile: load fp32 row-pairs, split into bf16x2 hi/lo ONCE ----
#pragma unroll
        for (int it = 0; it < 4; it++) {
            const int t  = it * 128 + tid;
            const int rp = t >> 4;            // row pair: rows 2rp, 2rp+1
            const int d4 = (t & 15) << 2;
            const float* vb = v + base + (size_t)(2 * rp) * (Hh * Dd) + d4;
            const float4 v0 = *(const float4*)(vb);
            const float4 v1 = *(const float4*)(vb + Hh * Dd);
            uint4 hi, lo;
            hi.x = packbf2(v0.x, v1.x);
            hi.y = packbf2(v0.y, v1.y);
            hi.z = packbf2(v0.z, v1.z);
            hi.w = packbf2(v0.w, v1.w);
            lo.x = packbf2(v0.x - __uint_as_float(hi.x << 16), v1.x - __uint_as_float(hi.x & 0xffff0000u));
            lo.y = packbf2(v0.y - __uint_as_float(hi.y << 16), v1.y - __uint_as_float(hi.y & 0xffff0000u));
            lo.z = packbf2(v0.z - __uint_as_float(hi.z << 16), v1.z - __uint_as_float(hi.z & 0xffff0000u));
            lo.w = packbf2(v0.w - __uint_as_float(hi.w << 16), v1.w - __uint_as_float(hi.w & 0xffff0000u));
            *(uint4*)(&sVhi[rp * VP + d4]) = hi;
            *(uint4*)(&sVlo[rp * VP + d4]) = lo;
        }
        __syncthreads();

        // ---- S = Q K^T (tf32 mma, K already tf32 in smem) ----
        float sacc[8][4];
#pragma unroll
        for (int nf = 0; nf < 8; nf++) {
            sacc[nf][0] = 0.f; sacc[nf][1] = 0.f; sacc[nf][2] = 0.f; sacc[nf][3] = 0.f;
#pragma unroll
            for (int ks = 0; ks < 8; ks++) {
                const uint32_t* kp = &sK[(nf * 8 + g) * PAD + ks * 8 + c];
                uint32_t bfr[2];
                bfr[0] = kp[0];
                bfr[1] = kp[4];
                mma_tf32(sacc[nf], qa[ks], bfr);
            }
        }

        // ---- scale + bias + causal mask ----
        const int kcb = j * BN;
        const bool diag = (j == qt);
#pragma unroll
        for (int nf = 0; nf < 8; nf++) {
            const int kc = kcb + nf * 8 + 2 * c;
            const float2 bb0 = __ldg((const float2*)(biasr0 + kc));
            const float2 bb1 = __ldg((const float2*)(biasr1 + kc));
            sacc[nf][0] = sacc[nf][0] * SCALE + bb0.x;
            sacc[nf][1] = sacc[nf][1] * SCALE + bb0.y;
            sacc[nf][2] = sacc[nf][2] * SCALE + bb1.x;
            sacc[nf][3] = sacc[nf][3] * SCALE + bb1.y;
            if (diag) {
                if (kc     > r0) sacc[nf][0] = NEGINF;
                if (kc + 1 > r0) sacc[nf][1] = NEGINF;
                if (kc     > r1) sacc[nf][2] = NEGINF;
                if (kc + 1 > r1) sacc[nf][3] = NEGINF;
            }
        }

        // ---- online softmax ----
        float rm0 = NEGINF, rm1 = NEGINF;
#pragma unroll
        for (int nf = 0; nf < 8; nf++) {
            rm0 = fmaxf(rm0, fmaxf(sacc[nf][0], sacc[nf][1]));
            rm1 = fmaxf(rm1, fmaxf(sacc[nf][2], sacc[nf][3]));
        }
        rm0 = fmaxf(rm0, __shfl_xor_sync(0xffffffffu, rm0, 1));
        rm0 = fmaxf(rm0, __shfl_xor_sync(0xffffffffu, rm0, 2));
        rm1 = fmaxf(rm1, __shfl_xor_sync(0xffffffffu, rm1, 1));
        rm1 = fmaxf(rm1, __shfl_xor_sync(0xffffffffu, rm1, 2));

        const float nm0 = fmaxf(m0, rm0), nm1 = fmaxf(m1, rm1);
        const float a0 = __expf(m0 - nm0), a1 = __expf(m1 - nm1);
        m0 = nm0; m1 = nm1;

        float rs0 = 0.f, rs1 = 0.f;
#pragma unroll
        for (int nf = 0; nf < 8; nf++) {
            sacc[nf][0] = __expf(sacc[nf][0] - nm0);
            sacc[nf][1] = __expf(sacc[nf][1] - nm0);
            sacc[nf][2] = __expf(sacc[nf][2] - nm1);
            sacc[nf][3] = __expf(sacc[nf][3] - nm1);
            rs0 += sacc[nf][0] + sacc[nf][1];
            rs1 += sacc[nf][2] + sacc[nf][3];
        }
        l0 = l0 * a0 + rs0;   // quad reduction deferred to epilogue
        l1 = l1 * a1 + rs1;

#pragma unroll
        for (int df = 0; df < 8; df++) {
            oacc[df][0] *= a0; oacc[df][1] *= a0;
            oacc[df][2] *= a1; oacc[df][3] *= a1;
        }

        // ---- O += P V  (split-bf16: p_hi*v_hi + p_hi*v_lo + p_lo*v_hi) ----
#pragma unroll
        for (int t = 0; t < 4; t++) {
            uint32_t ahi[4], alo[4];
            {
                const float p00 = sacc[2 * t][0],     p01 = sacc[2 * t][1];
                const float p10 = sacc[2 * t][2],     p11 = sacc[2 * t][3];
                const float p20 = sacc[2 * t + 1][0], p21 = sacc[2 * t + 1][1];
                const float p30 = sacc[2 * t + 1][2], p31 = sacc[2 * t + 1][3];
                ahi[0] = packbf2(p00, p01);
                ahi[1] = packbf2(p10, p11);
                ahi[2] = packbf2(p20, p21);
                ahi[3] = packbf2(p30, p31);
                alo[0] = packbf2(p00 - __uint_as_float(ahi[0] << 16),
                                 p01 - __uint_as_float(ahi[0] & 0xffff0000u));
                alo[1] = packbf2(p10 - __uint_as_float(ahi[1] << 16),
                                 p11 - __uint_as_float(ahi[1] & 0xffff0000u));
                alo[2] = packbf2(p20 - __uint_as_float(ahi[2] << 16),
                                 p21 - __uint_as_float(ahi[2] & 0xffff0000u));
                alo[3] = packbf2(p30 - __uint_as_float(ahi[3] << 16),
                                 p31 - __uint_as_float(ahi[3] & 0xffff0000u));
            }
            const int rpb = t * 8 + c;   // base row-pair index for this thread
#pragma unroll
            for (int df = 0; df < 8; df++) {
                const uint32_t* vh = &sVhi[rpb * VP + df * 8 + g];
                const uint32_t* vl = &sVlo[rpb * VP + df * 8 + g];
                uint32_t bhi[2], blo[2];
                bhi[0] = vh[0];
                bhi[1] = vh[4 * VP];
                blo[0] = vl[0];
                blo[1] = vl[4 * VP];
                mma_bf16(oacc[df], ahi, bhi);
                mma_bf16(oacc[df], ahi, blo);
                mma_bf16(oacc[df], alo, bhi);
            }
        }
    }

    // ---- epilogue: finish l reduction, normalize, store ----
    l0 += __shfl_xor_sync(0xffffffffu, l0, 1);
    l0 += __shfl_xor_sync(0xffffffffu, l0, 2);
    l1 += __shfl_xor_sync(0xffffffffu, l1, 1);
    l1 += __shfl_xor_sync(0xffffffffu, l1, 2);
    const float inv0 = 1.0f / l0;
    const float inv1 = 1.0f / l1;

    float* o0 = out + ((size_t)(b * Ss + r0) * Hh + h) * Dd;
    float* o1 = out + ((size_t)(b * Ss + r1) * Hh + h) * Dd;
#pragma unroll
    for (int df = 0; df < 8; df++) {
        const int dc = df * 8 + 2 * c;
        float2 w0, w1;
        w0.x = oacc[df][0] * inv0; w0.y = oacc[df][1] * inv0;
        w1.x = oacc[df][2] * inv1; w1.y = oacc[df][3] * inv1;
        *(float2*)(o0 + dc) = w0;
        *(float2*)(o1 + dc) = w1;
    }
}

} // namespace

extern "C" void kernel_launch(void* const* d_in, const int* in_sizes, int n_in,
                              void* d_out, int out_size)
{
    const float* q    = (const float*)d_in[0];
    const float* k    = (const float*)d_in[1];
    const float* v    = (const float*)d_in[2];
    const float* bias = (const float*)d_in[3];
    float* out        = (float*)d_out;

    const dim3 grid(Bb * Hh * (Ss / BM));  // 2048 CTAs
    fa_kernel<<<grid, 128>>>(q, k, v, bias, out);
}